// round 2
// baseline (speedup 1.0000x reference)
#include <cuda_runtime.h>
#include <math.h>

#define NTOK 16384
#define DDIM 2048
#define NEXP 64
#define TOPK 8

// output layout (floats)
#define OFF_TOP   0            // 16384*8
#define OFF_SC    131072       // 16384*64
#define OFF_IDX   1179648      // 16384*8
#define OFF_HIST  1310720      // 64
#define OFF_ENT   1310784      // 1

__global__ void zero_tail_kernel(float* out) {
    int i = threadIdx.x;
    if (i < 65) out[OFF_HIST + i] = 0.0f;
}

__global__ __launch_bounds__(256, 2)
void router_kernel(const float* __restrict__ x,
                   const float* __restrict__ W,
                   const float* __restrict__ bias,
                   float* __restrict__ out)
{
    __shared__ float As[16 * 68];      // [k][m], padded stride 68
    __shared__ float Bs[16 * 68];      // [k][n], padded stride 68
    __shared__ float Sc[64 * 65];      // scores tile [m][e], padded stride 65
    __shared__ float sbias[64];
    __shared__ float shist[64];

    const int tid = threadIdx.x;
    const int tx = tid & 15;           // 0..15 -> expert group (4 experts)
    const int ty = tid >> 4;           // 0..15 -> token group (4 tokens)
    const int m0 = blockIdx.x * 64;

    if (tid < 64) { sbias[tid] = bias[tid]; shist[tid] = 0.0f; }

    float acc[4][4];
#pragma unroll
    for (int i = 0; i < 4; i++)
#pragma unroll
        for (int j = 0; j < 4; j++) acc[i][j] = 0.0f;

    // global load pointers: each thread loads one float4 of x and one of W per tile
    const int lrow = tid >> 2;               // 0..63
    const int lk   = (tid & 3) << 2;         // 0,4,8,12
    const float* xg = x + (size_t)(m0 + lrow) * DDIM + lk;
    const float* wg = W + (size_t)lrow * DDIM + lk;

    for (int k0 = 0; k0 < DDIM; k0 += 16) {
        __syncthreads();
        float4 av = *(const float4*)(xg + k0);
        float4 bv = *(const float4*)(wg + k0);
        As[(lk + 0) * 68 + lrow] = av.x;
        As[(lk + 1) * 68 + lrow] = av.y;
        As[(lk + 2) * 68 + lrow] = av.z;
        As[(lk + 3) * 68 + lrow] = av.w;
        Bs[(lk + 0) * 68 + lrow] = bv.x;
        Bs[(lk + 1) * 68 + lrow] = bv.y;
        Bs[(lk + 2) * 68 + lrow] = bv.z;
        Bs[(lk + 3) * 68 + lrow] = bv.w;
        __syncthreads();
#pragma unroll
        for (int kk = 0; kk < 16; kk++) {
            float4 a = *(const float4*)&As[kk * 68 + ty * 4];
            float4 b = *(const float4*)&Bs[kk * 68 + tx * 4];
            acc[0][0] += a.x * b.x; acc[0][1] += a.x * b.y; acc[0][2] += a.x * b.z; acc[0][3] += a.x * b.w;
            acc[1][0] += a.y * b.x; acc[1][1] += a.y * b.y; acc[1][2] += a.y * b.z; acc[1][3] += a.y * b.w;
            acc[2][0] += a.z * b.x; acc[2][1] += a.z * b.y; acc[2][2] += a.z * b.z; acc[2][3] += a.z * b.w;
            acc[3][0] += a.w * b.x; acc[3][1] += a.w * b.y; acc[3][2] += a.w * b.z; acc[3][3] += a.w * b.w;
        }
    }

    // sigmoid -> smem tile + global scores output
    float* scores_out = out + OFF_SC;
#pragma unroll
    for (int i = 0; i < 4; i++) {
        int m = ty * 4 + i;
        float4 v;
        v.x = 1.0f / (1.0f + expf(-acc[i][0]));
        v.y = 1.0f / (1.0f + expf(-acc[i][1]));
        v.z = 1.0f / (1.0f + expf(-acc[i][2]));
        v.w = 1.0f / (1.0f + expf(-acc[i][3]));
        Sc[m * 65 + tx * 4 + 0] = v.x;
        Sc[m * 65 + tx * 4 + 1] = v.y;
        Sc[m * 65 + tx * 4 + 2] = v.z;
        Sc[m * 65 + tx * 4 + 3] = v.w;
        *(float4*)&scores_out[(size_t)(m0 + m) * NEXP + tx * 4] = v;
    }
    __syncthreads();

    // per-token top-8 selection (threads 0..63)
    if (tid < 64) {
        const int tok = m0 + tid;
        const float* row = &Sc[tid * 65];
        unsigned long long used = 0ULL;
        float ps[TOPK];
        int   pidx[TOPK];
        float ssum = 0.0f;
#pragma unroll
        for (int k = 0; k < TOPK; k++) {
            float best = -INFINITY;
            int bi = 0;
            for (int e = 0; e < NEXP; e++) {
                if ((used >> e) & 1ULL) continue;
                float v = row[e] + sbias[e];
                if (v > best) { best = v; bi = e; }   // strict > => lowest index wins ties
            }
            used |= (1ULL << bi);
            float s = row[bi];
            ps[k] = s; pidx[k] = bi; ssum += s;
            atomicAdd(&shist[bi], 1.0f);
        }
        float inv = 1.0f / (ssum + 1e-20f);
        float ent = 0.0f;
#pragma unroll
        for (int k = 0; k < TOPK; k++) {
            float p = ps[k] * inv;                    // ROUTE_SCALE == 1.0
            out[OFF_TOP + (size_t)tok * TOPK + k] = p;
            out[OFF_IDX + (size_t)tok * TOPK + k] = (float)pidx[k];
            ent += p * logf(p);
        }
        atomicAdd(&out[OFF_ENT], -ent * (1.0f / (float)NTOK));
    }
    __syncthreads();
    if (tid < 64) {
        float h = shist[tid];
        if (h != 0.0f) atomicAdd(&out[OFF_HIST + tid], h);
    }
}

extern "C" void kernel_launch(void* const* d_in, const int* in_sizes, int n_in,
                              void* d_out, int out_size) {
    const float* x    = (const float*)d_in[0];
    const float* W    = (const float*)d_in[1];
    const float* bias = (const float*)d_in[2];
    float* out = (float*)d_out;

    zero_tail_kernel<<<1, 96>>>(out);
    router_kernel<<<NTOK / 64, 256>>>(x, W, bias, out);
}